// round 1
// baseline (speedup 1.0000x reference)
#include <cuda_runtime.h>
#include <math.h>

#define BB 8
#define LL 16
#define T_TAB 65536
#define RMAX 256
#define N_PIX (RMAX * RMAX)

// Per-batch effective (modulated+demodulated) weights, produced by precompute_kernel.
__device__ float g_W0[BB][32][32];
__device__ float g_W1[BB][32][32];
__device__ float g_W2[BB][3][32];

// Instant-NGP resolution levels: round(16 * (256/16)^(l/15)) clipped to 256.
__constant__ int c_res[LL] = {16, 19, 23, 28, 34, 40, 49, 58,
                              70, 84, 102, 122, 147, 177, 213, 256};

// ---------------------------------------------------------------------------
// Precompute: style = s @ aw^T + ab ; wmod = w * style ; demod = rsqrt(sum wmod^2 + 1e-8)
// Effective weight row j: w[j][i] * style[i] * demod[j]. One block per batch.
// ---------------------------------------------------------------------------
__global__ void precompute_kernel(
    const float* __restrict__ s,
    const float* __restrict__ w0, const float* __restrict__ aw0, const float* __restrict__ ab0,
    const float* __restrict__ w1, const float* __restrict__ aw1, const float* __restrict__ ab1,
    const float* __restrict__ w2, const float* __restrict__ aw2, const float* __restrict__ ab2)
{
    int b = blockIdx.x;
    int tid = threadIdx.x;   // 128 threads
    __shared__ float st[3][32];

    const float* sv = s + b * 512;
    if (tid < 96) {
        int layer = tid >> 5;
        int i = tid & 31;
        const float* aw = (layer == 0) ? aw0 : (layer == 1) ? aw1 : aw2;
        const float* ab = (layer == 0) ? ab0 : (layer == 1) ? ab1 : ab2;
        const float* ar = aw + i * 512;
        float acc = 0.f;
        #pragma unroll 8
        for (int k = 0; k < 512; k++) acc += sv[k] * ar[k];
        st[layer][i] = acc + ab[i];
    }
    __syncthreads();

    if (tid < 32) {
        int j = tid;
        float wm[32]; float ss = 0.f;
        #pragma unroll
        for (int i = 0; i < 32; i++) { float v = w0[j * 32 + i] * st[0][i]; wm[i] = v; ss += v * v; }
        float d = rsqrtf(ss + 1e-8f);
        #pragma unroll
        for (int i = 0; i < 32; i++) g_W0[b][j][i] = wm[i] * d;
    } else if (tid < 64) {
        int j = tid - 32;
        float wm[32]; float ss = 0.f;
        #pragma unroll
        for (int i = 0; i < 32; i++) { float v = w1[j * 32 + i] * st[1][i]; wm[i] = v; ss += v * v; }
        float d = rsqrtf(ss + 1e-8f);
        #pragma unroll
        for (int i = 0; i < 32; i++) g_W1[b][j][i] = wm[i] * d;
    } else if (tid < 67) {
        int j = tid - 64;
        float wm[32]; float ss = 0.f;
        #pragma unroll
        for (int i = 0; i < 32; i++) { float v = w2[j * 32 + i] * st[2][i]; wm[i] = v; ss += v * v; }
        float d = rsqrtf(ss + 1e-8f);
        #pragma unroll
        for (int i = 0; i < 32; i++) g_W2[b][j][i] = wm[i] * d;
    }
}

// ---------------------------------------------------------------------------
// Fused: hash-grid bilinear encode (16 levels x 2 feats) + 32->32->32->3 MLP.
// One thread = one (batch, pixel). 16x16 pixel tiles per block for cell reuse.
// ---------------------------------------------------------------------------
__global__ void __launch_bounds__(256)
fused_kernel(const float* __restrict__ tables,
             const float* __restrict__ b0, const float* __restrict__ b1,
             const float* __restrict__ b2,
             float* __restrict__ out)
{
    __shared__ float sW0[32][32];
    __shared__ float sW1[32][32];
    __shared__ float sW2[3][32];
    __shared__ float sb0[32], sb1[32], sb2[3];

    const int b = blockIdx.y;
    const int tid = threadIdx.x;

    // Stage per-batch weights to shared.
    for (int k = tid; k < 1024; k += 256) {
        ((float*)sW0)[k] = ((const float*)g_W0[b])[k];
        ((float*)sW1)[k] = ((const float*)g_W1[b])[k];
    }
    if (tid < 96) ((float*)sW2)[tid] = ((const float*)g_W2[b])[tid];
    if (tid < 32) { sb0[tid] = b0[tid]; sb1[tid] = b1[tid]; }
    if (tid < 3)  sb2[tid] = b2[tid];
    __syncthreads();

    // 16x16 tile decomposition of the 256x256 image.
    const int tile = blockIdx.x;
    const int px = ((tile & 15) << 4) + (tid & 15);
    const int py = ((tile >> 4) << 4) + (tid >> 4);
    const float cx = (px + 0.5f) * (1.0f / RMAX);
    const float cy = (py + 0.5f) * (1.0f / RMAX);

    const float2* tab = (const float2*)tables + (size_t)b * (LL * T_TAB);

    float feat[2 * LL];
    #pragma unroll
    for (int l = 0; l < LL; l++) {
        const int res = c_res[l];
        const float rf = (float)(res - 1);
        float fpx = cx * rf, fpy = cy * rf;
        float fx0 = floorf(fpx), fy0 = floorf(fpy);
        float fx = fpx - fx0, fy = fpy - fy0;
        unsigned xi0 = (unsigned)fx0, yi0 = (unsigned)fy0;
        unsigned rm = (unsigned)(res - 1);
        unsigned xi1 = min(xi0 + 1u, rm), yi1 = min(yi0 + 1u, rm);
        unsigned hy0 = yi0 * 2654435761u, hy1 = yi1 * 2654435761u;
        const float2* tl = tab + l * T_TAB;
        float2 g00 = __ldg(tl + ((xi0 ^ hy0) & 65535u));
        float2 g10 = __ldg(tl + ((xi1 ^ hy0) & 65535u));
        float2 g01 = __ldg(tl + ((xi0 ^ hy1) & 65535u));
        float2 g11 = __ldg(tl + ((xi1 ^ hy1) & 65535u));
        float w00 = (1.f - fx) * (1.f - fy);
        float w10 = fx * (1.f - fy);
        float w01 = (1.f - fx) * fy;
        float w11 = fx * fy;
        feat[2 * l]     = g00.x * w00 + g10.x * w10 + g01.x * w01 + g11.x * w11;
        feat[2 * l + 1] = g00.y * w00 + g10.y * w10 + g01.y * w01 + g11.y * w11;
    }

    // Layer 0: 32 -> 32, ReLU
    float h0[32];
    #pragma unroll
    for (int j = 0; j < 32; j++) {
        const float4* wr = (const float4*)sW0[j];
        float acc = sb0[j];
        #pragma unroll
        for (int q = 0; q < 8; q++) {
            float4 wv = wr[q];
            acc += wv.x * feat[4 * q] + wv.y * feat[4 * q + 1]
                 + wv.z * feat[4 * q + 2] + wv.w * feat[4 * q + 3];
        }
        h0[j] = fmaxf(acc, 0.f);
    }

    // Layer 1: 32 -> 32, ReLU
    float h1[32];
    #pragma unroll
    for (int j = 0; j < 32; j++) {
        const float4* wr = (const float4*)sW1[j];
        float acc = sb1[j];
        #pragma unroll
        for (int q = 0; q < 8; q++) {
            float4 wv = wr[q];
            acc += wv.x * h0[4 * q] + wv.y * h0[4 * q + 1]
                 + wv.z * h0[4 * q + 2] + wv.w * h0[4 * q + 3];
        }
        h1[j] = fmaxf(acc, 0.f);
    }

    // Layer 2: 32 -> 3, tanh
    float o[3];
    #pragma unroll
    for (int j = 0; j < 3; j++) {
        const float4* wr = (const float4*)sW2[j];
        float acc = sb2[j];
        #pragma unroll
        for (int q = 0; q < 8; q++) {
            float4 wv = wr[q];
            acc += wv.x * h1[4 * q] + wv.y * h1[4 * q + 1]
                 + wv.z * h1[4 * q + 2] + wv.w * h1[4 * q + 3];
        }
        o[j] = tanhf(acc);
    }

    // out[b][c][y][x]
    size_t base = (size_t)b * 3 * N_PIX + (size_t)py * RMAX + px;
    out[base]             = o[0];
    out[base + N_PIX]     = o[1];
    out[base + 2 * N_PIX] = o[2];
}

// ---------------------------------------------------------------------------
// Launch
// ---------------------------------------------------------------------------
extern "C" void kernel_launch(void* const* d_in, const int* in_sizes, int n_in,
                              void* d_out, int out_size)
{
    const float* x   = (const float*)d_in[0];
    const float* s   = (const float*)d_in[1];
    // d_in[2] = coords (recomputed analytically on device)
    const float* w0  = (const float*)d_in[3];
    const float* aw0 = (const float*)d_in[4];
    const float* ab0 = (const float*)d_in[5];
    const float* b0  = (const float*)d_in[6];
    const float* w1  = (const float*)d_in[7];
    const float* aw1 = (const float*)d_in[8];
    const float* ab1 = (const float*)d_in[9];
    const float* b1  = (const float*)d_in[10];
    const float* w2  = (const float*)d_in[11];
    const float* aw2 = (const float*)d_in[12];
    const float* ab2 = (const float*)d_in[13];
    const float* b2  = (const float*)d_in[14];
    float* out = (float*)d_out;

    precompute_kernel<<<BB, 128>>>(s, w0, aw0, ab0, w1, aw1, ab1, w2, aw2, ab2);
    fused_kernel<<<dim3(256, BB), 256>>>(x, b0, b1, b2, out);
}

// round 2
// speedup vs baseline: 1.2061x; 1.2061x over previous
#include <cuda_runtime.h>
#include <math.h>

#define BB 8
#define LL 16
#define T_TAB 65536
#define RMAX 256
#define N_PIX (RMAX * RMAX)
#define NCELLS 211538

// Instant-NGP resolution levels and cumulative dense-grid offsets.
__constant__ int c_res[LL] = {16, 19, 23, 28, 34, 40, 49, 58,
                              70, 84, 102, 122, 147, 177, 213, 256};
__constant__ int c_off[LL] = {0, 256, 617, 1146, 1930, 3086, 4686, 7087,
                              10451, 15351, 22407, 32811, 47695, 69304, 100633, 146002};

// Dense (de-hashed) grids: g_dense[b][cell] = table[b][l][hash(x,y)]
__device__ float2 g_dense[BB][NCELLS];            // 13.5 MB scratch

// Per-batch effective weights. W0p/W1p stored TRANSPOSED: g_Wp[b][i][j] = Weff[j][i]
// so a float2 at [i][2jp] = (Weff[2jp][i], Weff[2jp+1][i]) feeds fma.f32x2 directly.
__device__ float g_W0p[BB][32][32];
__device__ float g_W1p[BB][32][32];
__device__ float g_W2[BB][3][32];                 // row-major (scalar layer 2)

// ---------------------------------------------------------------------------
// f32x2 packed-math helpers
// ---------------------------------------------------------------------------
__device__ __forceinline__ unsigned long long pk2(float lo, float hi) {
    unsigned long long r;
    asm("mov.b64 %0, {%1, %2};" : "=l"(r) : "f"(lo), "f"(hi));
    return r;
}
__device__ __forceinline__ void upk2(unsigned long long v, float& lo, float& hi) {
    asm("mov.b64 {%0, %1}, %2;" : "=f"(lo), "=f"(hi) : "l"(v));
}
__device__ __forceinline__ unsigned long long fma2(unsigned long long a,
                                                   unsigned long long b,
                                                   unsigned long long c) {
    unsigned long long d;
    asm("fma.rn.f32x2 %0, %1, %2, %3;" : "=l"(d) : "l"(a), "l"(b), "l"(c));
    return d;
}

// ---------------------------------------------------------------------------
// Precompute: style -> modulated+demodulated effective weights (8 blocks).
// ---------------------------------------------------------------------------
__global__ void precompute_kernel(
    const float* __restrict__ s,
    const float* __restrict__ w0, const float* __restrict__ aw0, const float* __restrict__ ab0,
    const float* __restrict__ w1, const float* __restrict__ aw1, const float* __restrict__ ab1,
    const float* __restrict__ w2, const float* __restrict__ aw2, const float* __restrict__ ab2)
{
    const int b = blockIdx.x;
    const int tid = threadIdx.x;       // 256
    const int wid = tid >> 5, lane = tid & 31;
    __shared__ float st[96];

    const float* sv = s + b * 512;
    for (int o = wid; o < 96; o += 8) {
        const int layer = o >> 5, i = o & 31;
        const float* aw = (layer == 0) ? aw0 : (layer == 1) ? aw1 : aw2;
        const float* ab = (layer == 0) ? ab0 : (layer == 1) ? ab1 : ab2;
        const float* row = aw + i * 512;
        float acc = 0.f;
        #pragma unroll 4
        for (int k = lane; k < 512; k += 32) acc += sv[k] * row[k];
        #pragma unroll
        for (int d = 16; d > 0; d >>= 1) acc += __shfl_xor_sync(0xFFFFFFFFu, acc, d);
        if (lane == 0) st[o] = acc + ab[i];
    }
    __syncthreads();

    if (tid < 32) {
        const int j = tid;
        float wm[32]; float ss = 0.f;
        #pragma unroll
        for (int i = 0; i < 32; i++) { float v = w0[j * 32 + i] * st[i]; wm[i] = v; ss += v * v; }
        float d = rsqrtf(ss + 1e-8f);
        #pragma unroll
        for (int i = 0; i < 32; i++) g_W0p[b][i][j] = wm[i] * d;   // transposed
    } else if (tid < 64) {
        const int j = tid - 32;
        float wm[32]; float ss = 0.f;
        #pragma unroll
        for (int i = 0; i < 32; i++) { float v = w1[j * 32 + i] * st[32 + i]; wm[i] = v; ss += v * v; }
        float d = rsqrtf(ss + 1e-8f);
        #pragma unroll
        for (int i = 0; i < 32; i++) g_W1p[b][i][j] = wm[i] * d;   // transposed
    } else if (tid < 67) {
        const int j = tid - 64;
        float wm[32]; float ss = 0.f;
        #pragma unroll
        for (int i = 0; i < 32; i++) { float v = w2[j * 32 + i] * st[64 + i]; wm[i] = v; ss += v * v; }
        float d = rsqrtf(ss + 1e-8f);
        #pragma unroll
        for (int i = 0; i < 32; i++) g_W2[b][j][i] = wm[i] * d;    // row-major
    }
}

// ---------------------------------------------------------------------------
// Prepass: de-hash tables into dense per-level grids (1.7M cheap gathers).
// ---------------------------------------------------------------------------
__global__ void __launch_bounds__(256)
densify_kernel(const float* __restrict__ tables)
{
    const int c = blockIdx.x * 256 + threadIdx.x;
    const int b = blockIdx.y;
    if (c >= NCELLS) return;
    int l = 0;
    #pragma unroll
    for (int k = 1; k < LL; k++) l += (c >= c_off[k]);
    const int local = c - c_off[l];
    const int r = c_res[l];
    const int y = local / r;
    const int x = local - y * r;
    const unsigned idx = ((unsigned)x ^ ((unsigned)y * 2654435761u)) & 65535u;
    const float2* tab = (const float2*)tables + ((size_t)b * LL + l) * T_TAB;
    g_dense[b][c] = __ldg(tab + idx);
}

// ---------------------------------------------------------------------------
// Fused: dense-grid bilinear encode + 32->32->32->3 MLP (f32x2 packed).
// One thread = one (batch, pixel). 16x8 pixel tiles per 128-thread block.
// ---------------------------------------------------------------------------
__global__ void __launch_bounds__(128)
fused_kernel(const float* __restrict__ b0, const float* __restrict__ b1,
             const float* __restrict__ b2, float* __restrict__ out)
{
    __shared__ __align__(16) float sW0p[32][32];
    __shared__ __align__(16) float sW1p[32][32];
    __shared__ __align__(16) float sW2[3][32];
    __shared__ float sb0[32], sb1[32], sb2[3];

    const int b = blockIdx.y;
    const int tid = threadIdx.x;

    for (int k = tid; k < 1024; k += 128) {
        ((float*)sW0p)[k] = ((const float*)g_W0p[b])[k];
        ((float*)sW1p)[k] = ((const float*)g_W1p[b])[k];
    }
    if (tid < 96) ((float*)sW2)[tid] = ((const float*)g_W2[b])[tid];
    if (tid < 32) { sb0[tid] = b0[tid]; sb1[tid] = b1[tid]; }
    if (tid < 3)  sb2[tid] = b2[tid];
    __syncthreads();

    // 16x8 tile decomposition; warp = 16x2 strip (x-contiguous for coalescing).
    const int tile = blockIdx.x;                  // 0..511
    const int px = ((tile & 15) << 4) + (tid & 15);
    const int py = ((tile >> 4) << 3) + (tid >> 4);
    const float cx = (px + 0.5f) * (1.0f / RMAX);
    const float cy = (py + 0.5f) * (1.0f / RMAX);

    const unsigned long long* dense = (const unsigned long long*)g_dense[b];

    // Layer-0 accumulators: 16 packed pairs = outputs (2jp, 2jp+1).
    unsigned long long acc[16];
    #pragma unroll
    for (int jp = 0; jp < 16; jp++) acc[jp] = pk2(sb0[2 * jp], sb0[2 * jp + 1]);

    #pragma unroll
    for (int l = 0; l < LL; l++) {
        const int r = c_res[l];
        const float rf = (float)(r - 1);
        const float fpx = cx * rf, fpy = cy * rf;
        const float fx0 = floorf(fpx), fy0 = floorf(fpy);
        const float fx = fpx - fx0, fy = fpy - fy0;
        const int x0 = (int)fx0, y0 = (int)fy0;
        // pixel centers guarantee x0 <= r-2, y0 <= r-2: no clamp needed
        const int a00 = c_off[l] + y0 * r + x0;
        const unsigned long long g00 = dense[a00];
        const unsigned long long g10 = dense[a00 + 1];
        const unsigned long long g01 = dense[a00 + r];
        const unsigned long long g11 = dense[a00 + r + 1];
        const float w00 = (1.f - fx) * (1.f - fy);
        const float w10 = fx * (1.f - fy);
        const float w01 = (1.f - fx) * fy;
        const float w11 = fx * fy;
        unsigned long long f2 = fma2(g00, pk2(w00, w00), 0ULL);
        f2 = fma2(g10, pk2(w10, w10), f2);
        f2 = fma2(g01, pk2(w01, w01), f2);
        f2 = fma2(g11, pk2(w11, w11), f2);
        float f0, f1; upk2(f2, f0, f1);

        // Feed features (inputs i=2l, 2l+1) straight into layer 0.
        const unsigned long long f0b = pk2(f0, f0);
        const unsigned long long f1b = pk2(f1, f1);
        const ulonglong2* wr0 = (const ulonglong2*)sW0p[2 * l];
        const ulonglong2* wr1 = (const ulonglong2*)sW0p[2 * l + 1];
        #pragma unroll
        for (int q = 0; q < 8; q++) {
            ulonglong2 wa = wr0[q];
            acc[2 * q]     = fma2(wa.x, f0b, acc[2 * q]);
            acc[2 * q + 1] = fma2(wa.y, f0b, acc[2 * q + 1]);
        }
        #pragma unroll
        for (int q = 0; q < 8; q++) {
            ulonglong2 wb = wr1[q];
            acc[2 * q]     = fma2(wb.x, f1b, acc[2 * q]);
            acc[2 * q + 1] = fma2(wb.y, f1b, acc[2 * q + 1]);
        }
    }

    // ReLU -> h0
    float h0[32];
    #pragma unroll
    for (int jp = 0; jp < 16; jp++) {
        float a, c; upk2(acc[jp], a, c);
        h0[2 * jp] = fmaxf(a, 0.f);
        h0[2 * jp + 1] = fmaxf(c, 0.f);
    }

    // Layer 1 (packed)
    unsigned long long acc1[16];
    #pragma unroll
    for (int jp = 0; jp < 16; jp++) acc1[jp] = pk2(sb1[2 * jp], sb1[2 * jp + 1]);
    #pragma unroll
    for (int i = 0; i < 32; i++) {
        const unsigned long long fb = pk2(h0[i], h0[i]);
        const ulonglong2* wr = (const ulonglong2*)sW1p[i];
        #pragma unroll
        for (int q = 0; q < 8; q++) {
            ulonglong2 w = wr[q];
            acc1[2 * q]     = fma2(w.x, fb, acc1[2 * q]);
            acc1[2 * q + 1] = fma2(w.y, fb, acc1[2 * q + 1]);
        }
    }
    float h1[32];
    #pragma unroll
    for (int jp = 0; jp < 16; jp++) {
        float a, c; upk2(acc1[jp], a, c);
        h1[2 * jp] = fmaxf(a, 0.f);
        h1[2 * jp + 1] = fmaxf(c, 0.f);
    }

    // Layer 2: 32 -> 3, tanh (scalar)
    float o[3];
    #pragma unroll
    for (int j = 0; j < 3; j++) {
        const float4* wr = (const float4*)sW2[j];
        float a = sb2[j];
        #pragma unroll
        for (int q = 0; q < 8; q++) {
            float4 wv = wr[q];
            a += wv.x * h1[4 * q] + wv.y * h1[4 * q + 1]
               + wv.z * h1[4 * q + 2] + wv.w * h1[4 * q + 3];
        }
        o[j] = tanhf(a);
    }

    size_t base = (size_t)b * 3 * N_PIX + (size_t)py * RMAX + px;
    out[base]             = o[0];
    out[base + N_PIX]     = o[1];
    out[base + 2 * N_PIX] = o[2];
}

// ---------------------------------------------------------------------------
// Launch
// ---------------------------------------------------------------------------
extern "C" void kernel_launch(void* const* d_in, const int* in_sizes, int n_in,
                              void* d_out, int out_size)
{
    const float* x   = (const float*)d_in[0];
    const float* s   = (const float*)d_in[1];
    // d_in[2] = coords (recomputed analytically)
    const float* w0  = (const float*)d_in[3];
    const float* aw0 = (const float*)d_in[4];
    const float* ab0 = (const float*)d_in[5];
    const float* b0  = (const float*)d_in[6];
    const float* w1  = (const float*)d_in[7];
    const float* aw1 = (const float*)d_in[8];
    const float* ab1 = (const float*)d_in[9];
    const float* b1  = (const float*)d_in[10];
    const float* w2  = (const float*)d_in[11];
    const float* aw2 = (const float*)d_in[12];
    const float* ab2 = (const float*)d_in[13];
    const float* b2  = (const float*)d_in[14];
    float* out = (float*)d_out;

    precompute_kernel<<<BB, 256>>>(s, w0, aw0, ab0, w1, aw1, ab1, w2, aw2, ab2);
    densify_kernel<<<dim3((NCELLS + 255) / 256, BB), 256>>>(x);
    fused_kernel<<<dim3(512, BB), 128>>>(b0, b1, b2, out);
}

// round 3
// speedup vs baseline: 1.5943x; 1.3219x over previous
#include <cuda_runtime.h>
#include <math.h>

#define BB 8
#define LL 16
#define T_TAB 65536
#define RMAX 256
#define N_PIX (RMAX * RMAX)
#define NCELLS 211538

__constant__ int c_res[LL] = {16, 19, 23, 28, 34, 40, 49, 58,
                              70, 84, 102, 122, 147, 177, 213, 256};
__constant__ int c_off[LL] = {0, 256, 617, 1146, 1930, 3086, 4686, 7087,
                              10451, 15351, 22407, 32811, 47695, 69304, 100633, 146002};

// Dense (de-hashed) grids.
__device__ float2 g_dense[BB][NCELLS];

// style[b][layer*32 + i]
__device__ float g_style[BB][96];

// Effective weights. W0p/W1p TRANSPOSED: g_Wp[b][i][j] = Weff[j][i].
__device__ float g_W0p[BB][32][32];
__device__ float g_W1p[BB][32][32];
__device__ float g_W2[BB][3][32];

// ---------------------------------------------------------------------------
// f32x2 helpers
// ---------------------------------------------------------------------------
__device__ __forceinline__ unsigned long long pk2(float lo, float hi) {
    unsigned long long r;
    asm("mov.b64 %0, {%1, %2};" : "=l"(r) : "f"(lo), "f"(hi));
    return r;
}
__device__ __forceinline__ void upk2(unsigned long long v, float& lo, float& hi) {
    asm("mov.b64 {%0, %1}, %2;" : "=f"(lo), "=f"(hi) : "l"(v));
}
__device__ __forceinline__ unsigned long long fma2(unsigned long long a,
                                                   unsigned long long b,
                                                   unsigned long long c) {
    unsigned long long d;
    asm("fma.rn.f32x2 %0, %1, %2, %3;" : "=l"(d) : "l"(a), "l"(b), "l"(c));
    return d;
}

// ---------------------------------------------------------------------------
// Style projection: style = s @ aw^T + ab. Grid (3 layers, 8 batches),
// 1024 threads, one warp per row, float4 loads + shuffle reduce.
// ---------------------------------------------------------------------------
__global__ void __launch_bounds__(1024)
style_kernel(const float* __restrict__ s,
             const float* __restrict__ aw0, const float* __restrict__ ab0,
             const float* __restrict__ aw1, const float* __restrict__ ab1,
             const float* __restrict__ aw2, const float* __restrict__ ab2)
{
    const int layer = blockIdx.x;
    const int b = blockIdx.y;
    const int wid = threadIdx.x >> 5, lane = threadIdx.x & 31;

    const float* aw = (layer == 0) ? aw0 : (layer == 1) ? aw1 : aw2;
    const float* ab = (layer == 0) ? ab0 : (layer == 1) ? ab1 : ab2;

    const float4* sv4 = (const float4*)(s + b * 512);
    const float4* rw4 = (const float4*)(aw + wid * 512);
    float acc = 0.f;
    #pragma unroll
    for (int it = 0; it < 4; it++) {
        float4 a = __ldg(sv4 + it * 32 + lane);
        float4 w = __ldg(rw4 + it * 32 + lane);
        acc += a.x * w.x + a.y * w.y + a.z * w.z + a.w * w.w;
    }
    #pragma unroll
    for (int d = 16; d > 0; d >>= 1) acc += __shfl_xor_sync(0xFFFFFFFFu, acc, d);
    if (lane == 0) g_style[b][layer * 32 + wid] = acc + __ldg(ab + wid);
}

// ---------------------------------------------------------------------------
// Weight modulation + demodulation. Grid (8 batches), 96 threads.
// ---------------------------------------------------------------------------
__global__ void __launch_bounds__(128)
weights_kernel(const float* __restrict__ w0, const float* __restrict__ w1,
               const float* __restrict__ w2)
{
    const int b = blockIdx.x;
    const int tid = threadIdx.x;

    if (tid < 32) {
        const int j = tid;
        float wm[32]; float ss = 0.f;
        #pragma unroll
        for (int i = 0; i < 32; i++) { float v = w0[j * 32 + i] * g_style[b][i]; wm[i] = v; ss += v * v; }
        float d = rsqrtf(ss + 1e-8f);
        #pragma unroll
        for (int i = 0; i < 32; i++) g_W0p[b][i][j] = wm[i] * d;
    } else if (tid < 64) {
        const int j = tid - 32;
        float wm[32]; float ss = 0.f;
        #pragma unroll
        for (int i = 0; i < 32; i++) { float v = w1[j * 32 + i] * g_style[b][32 + i]; wm[i] = v; ss += v * v; }
        float d = rsqrtf(ss + 1e-8f);
        #pragma unroll
        for (int i = 0; i < 32; i++) g_W1p[b][i][j] = wm[i] * d;
    } else if (tid < 67) {
        const int j = tid - 64;
        float wm[32]; float ss = 0.f;
        #pragma unroll
        for (int i = 0; i < 32; i++) { float v = w2[j * 32 + i] * g_style[b][64 + i]; wm[i] = v; ss += v * v; }
        float d = rsqrtf(ss + 1e-8f);
        #pragma unroll
        for (int i = 0; i < 32; i++) g_W2[b][j][i] = wm[i] * d;
    }
}

// ---------------------------------------------------------------------------
// De-hash tables into dense per-level grids.
// ---------------------------------------------------------------------------
__global__ void __launch_bounds__(256)
densify_kernel(const float* __restrict__ tables)
{
    const int c = blockIdx.x * 256 + threadIdx.x;
    const int b = blockIdx.y;
    if (c >= NCELLS) return;
    int l = 0;
    #pragma unroll
    for (int k = 1; k < LL; k++) l += (c >= c_off[k]);
    const int local = c - c_off[l];
    const int r = c_res[l];
    const int y = local / r;
    const int x = local - y * r;
    const unsigned idx = ((unsigned)x ^ ((unsigned)y * 2654435761u)) & 65535u;
    const float2* tab = (const float2*)tables + ((size_t)b * LL + l) * T_TAB;
    g_dense[b][c] = __ldg(tab + idx);
}

// ---------------------------------------------------------------------------
// Fused: dense bilinear encode + MLP, 2 pixels (x-pair) per thread.
// Block = 128 threads covering a 32x8 pixel tile.
// ---------------------------------------------------------------------------
__global__ void __launch_bounds__(128)
fused_kernel(const float* __restrict__ b0, const float* __restrict__ b1,
             const float* __restrict__ b2, float* __restrict__ out)
{
    __shared__ __align__(16) float sW0p[32][32];
    __shared__ __align__(16) float sW1p[32][32];
    __shared__ __align__(16) float sW2[3][32];
    __shared__ float sb0[32], sb1[32], sb2[3];

    const int b = blockIdx.y;
    const int tid = threadIdx.x;

    for (int k = tid; k < 1024; k += 128) {
        ((float*)sW0p)[k] = ((const float*)g_W0p[b])[k];
        ((float*)sW1p)[k] = ((const float*)g_W1p[b])[k];
    }
    if (tid < 96) ((float*)sW2)[tid] = ((const float*)g_W2[b])[tid];
    if (tid < 32) { sb0[tid] = b0[tid]; sb1[tid] = b1[tid]; }
    if (tid < 3)  sb2[tid] = b2[tid];
    __syncthreads();

    // 32x8 tiles: 8 across, 32 down.
    const int tile = blockIdx.x;                  // 0..255
    const int px = ((tile & 7) << 5) + ((tid & 15) << 1);   // even
    const int py = ((tile >> 3) << 3) + (tid >> 4);
    const float cxA = (px + 0.5f) * (1.0f / RMAX);
    const float cxB = (px + 1.5f) * (1.0f / RMAX);
    const float cy  = (py + 0.5f) * (1.0f / RMAX);

    const unsigned long long* dense = (const unsigned long long*)g_dense[b];

    unsigned long long accA[16], accB[16];
    #pragma unroll
    for (int jp = 0; jp < 16; jp++) {
        unsigned long long bb = pk2(sb0[2 * jp], sb0[2 * jp + 1]);
        accA[jp] = bb; accB[jp] = bb;
    }

    #pragma unroll
    for (int l = 0; l < LL; l++) {
        const int r = c_res[l];
        const float rf = (float)(r - 1);
        const float fpy = cy * rf;
        const float fy0 = floorf(fpy);
        const float fy = fpy - fy0;
        const int y0 = (int)fy0;
        const int rowbase = c_off[l] + y0 * r;

        float fA0, fA1, fB0, fB1;
        {
            const float fpx = cxA * rf;
            const float fx0f = floorf(fpx);
            const float fx = fpx - fx0f;
            const int a00 = rowbase + (int)fx0f;
            const unsigned long long g00 = dense[a00];
            const unsigned long long g10 = dense[a00 + 1];
            const unsigned long long g01 = dense[a00 + r];
            const unsigned long long g11 = dense[a00 + r + 1];
            const float w00 = (1.f - fx) * (1.f - fy);
            const float w10 = fx * (1.f - fy);
            const float w01 = (1.f - fx) * fy;
            const float w11 = fx * fy;
            unsigned long long f2 = fma2(g00, pk2(w00, w00), 0ULL);
            f2 = fma2(g10, pk2(w10, w10), f2);
            f2 = fma2(g01, pk2(w01, w01), f2);
            f2 = fma2(g11, pk2(w11, w11), f2);
            upk2(f2, fA0, fA1);
        }
        {
            const float fpx = cxB * rf;
            const float fx0f = floorf(fpx);
            const float fx = fpx - fx0f;
            const int a00 = rowbase + (int)fx0f;
            const unsigned long long g00 = dense[a00];
            const unsigned long long g10 = dense[a00 + 1];
            const unsigned long long g01 = dense[a00 + r];
            const unsigned long long g11 = dense[a00 + r + 1];
            const float w00 = (1.f - fx) * (1.f - fy);
            const float w10 = fx * (1.f - fy);
            const float w01 = (1.f - fx) * fy;
            const float w11 = fx * fy;
            unsigned long long f2 = fma2(g00, pk2(w00, w00), 0ULL);
            f2 = fma2(g10, pk2(w10, w10), f2);
            f2 = fma2(g01, pk2(w01, w01), f2);
            f2 = fma2(g11, pk2(w11, w11), f2);
            upk2(f2, fB0, fB1);
        }

        const unsigned long long fA0b = pk2(fA0, fA0), fA1b = pk2(fA1, fA1);
        const unsigned long long fB0b = pk2(fB0, fB0), fB1b = pk2(fB1, fB1);
        const ulonglong2* wr0 = (const ulonglong2*)sW0p[2 * l];
        const ulonglong2* wr1 = (const ulonglong2*)sW0p[2 * l + 1];
        #pragma unroll
        for (int q = 0; q < 8; q++) {
            ulonglong2 wa = wr0[q];
            accA[2 * q]     = fma2(wa.x, fA0b, accA[2 * q]);
            accA[2 * q + 1] = fma2(wa.y, fA0b, accA[2 * q + 1]);
            accB[2 * q]     = fma2(wa.x, fB0b, accB[2 * q]);
            accB[2 * q + 1] = fma2(wa.y, fB0b, accB[2 * q + 1]);
        }
        #pragma unroll
        for (int q = 0; q < 8; q++) {
            ulonglong2 wb = wr1[q];
            accA[2 * q]     = fma2(wb.x, fA1b, accA[2 * q]);
            accA[2 * q + 1] = fma2(wb.y, fA1b, accA[2 * q + 1]);
            accB[2 * q]     = fma2(wb.x, fB1b, accB[2 * q]);
            accB[2 * q + 1] = fma2(wb.y, fB1b, accB[2 * q + 1]);
        }
    }

    // ReLU -> h0 (both pixels), reuse acc regs for layer 1.
    float h0A[32], h0B[32];
    #pragma unroll
    for (int jp = 0; jp < 16; jp++) {
        float a, c;
        upk2(accA[jp], a, c);
        h0A[2 * jp] = fmaxf(a, 0.f); h0A[2 * jp + 1] = fmaxf(c, 0.f);
        upk2(accB[jp], a, c);
        h0B[2 * jp] = fmaxf(a, 0.f); h0B[2 * jp + 1] = fmaxf(c, 0.f);
    }

    #pragma unroll
    for (int jp = 0; jp < 16; jp++) {
        unsigned long long bb = pk2(sb1[2 * jp], sb1[2 * jp + 1]);
        accA[jp] = bb; accB[jp] = bb;
    }
    #pragma unroll
    for (int i = 0; i < 32; i++) {
        const unsigned long long fa = pk2(h0A[i], h0A[i]);
        const unsigned long long fb = pk2(h0B[i], h0B[i]);
        const ulonglong2* wr = (const ulonglong2*)sW1p[i];
        #pragma unroll
        for (int q = 0; q < 8; q++) {
            ulonglong2 w = wr[q];
            accA[2 * q]     = fma2(w.x, fa, accA[2 * q]);
            accA[2 * q + 1] = fma2(w.y, fa, accA[2 * q + 1]);
            accB[2 * q]     = fma2(w.x, fb, accB[2 * q]);
            accB[2 * q + 1] = fma2(w.y, fb, accB[2 * q + 1]);
        }
    }

    float h1A[32], h1B[32];
    #pragma unroll
    for (int jp = 0; jp < 16; jp++) {
        float a, c;
        upk2(accA[jp], a, c);
        h1A[2 * jp] = fmaxf(a, 0.f); h1A[2 * jp + 1] = fmaxf(c, 0.f);
        upk2(accB[jp], a, c);
        h1B[2 * jp] = fmaxf(a, 0.f); h1B[2 * jp + 1] = fmaxf(c, 0.f);
    }

    // Layer 2: 32 -> 3, tanh. Pack pixel pair into f32x2 lanes.
    float oA[3], oB[3];
    #pragma unroll
    for (int j = 0; j < 3; j++) {
        const float4* wr = (const float4*)sW2[j];
        unsigned long long a2 = pk2(sb2[j], sb2[j]);
        #pragma unroll
        for (int q = 0; q < 8; q++) {
            float4 wv = wr[q];
            a2 = fma2(pk2(h1A[4 * q],     h1B[4 * q]),     pk2(wv.x, wv.x), a2);
            a2 = fma2(pk2(h1A[4 * q + 1], h1B[4 * q + 1]), pk2(wv.y, wv.y), a2);
            a2 = fma2(pk2(h1A[4 * q + 2], h1B[4 * q + 2]), pk2(wv.z, wv.z), a2);
            a2 = fma2(pk2(h1A[4 * q + 3], h1B[4 * q + 3]), pk2(wv.w, wv.w), a2);
        }
        float a, c; upk2(a2, a, c);
        oA[j] = tanhf(a); oB[j] = tanhf(c);
    }

    size_t base = (size_t)b * 3 * N_PIX + (size_t)py * RMAX + px;
    *(float2*)(out + base)             = make_float2(oA[0], oB[0]);
    *(float2*)(out + base + N_PIX)     = make_float2(oA[1], oB[1]);
    *(float2*)(out + base + 2 * N_PIX) = make_float2(oA[2], oB[2]);
}

// ---------------------------------------------------------------------------
// Launch
// ---------------------------------------------------------------------------
extern "C" void kernel_launch(void* const* d_in, const int* in_sizes, int n_in,
                              void* d_out, int out_size)
{
    const float* x   = (const float*)d_in[0];
    const float* s   = (const float*)d_in[1];
    const float* w0  = (const float*)d_in[3];
    const float* aw0 = (const float*)d_in[4];
    const float* ab0 = (const float*)d_in[5];
    const float* b0  = (const float*)d_in[6];
    const float* w1  = (const float*)d_in[7];
    const float* aw1 = (const float*)d_in[8];
    const float* ab1 = (const float*)d_in[9];
    const float* b1  = (const float*)d_in[10];
    const float* w2  = (const float*)d_in[11];
    const float* aw2 = (const float*)d_in[12];
    const float* ab2 = (const float*)d_in[13];
    const float* b2  = (const float*)d_in[14];
    float* out = (float*)d_out;

    style_kernel<<<dim3(3, BB), 1024>>>(s, aw0, ab0, aw1, ab1, aw2, ab2);
    densify_kernel<<<dim3((NCELLS + 255) / 256, BB), 256>>>(x);
    weights_kernel<<<BB, 128>>>(w0, w1, w2);
    fused_kernel<<<dim3(256, BB), 128>>>(b0, b1, b2, out);
}